// round 15
// baseline (speedup 1.0000x reference)
#include <cuda_runtime.h>
#include <cuda_fp16.h>
#include <math.h>
#include <stdint.h>

#define S_  2048
#define E_  4096
#define H_  32
#define D_  128
#define NB_ 32
#define BS_ 64

// packed fp16 hi/lo row strides (bytes): K elems -> (K/32) chunks of 128B [hi64|lo64]
#define PROW_E 16384      // K = 4096
#define PROW_S 8192       // K = 2048

// ---------------- scratch ---------------------------------------------------
static __device__ float g_q[(size_t)S_ * E_];
static __device__ float g_k[(size_t)S_ * E_];
static __device__ float g_v[(size_t)S_ * E_];
static __device__ float g_scores[(size_t)H_ * S_ * S_];
static __device__ float g_bmax[H_ * NB_ * NB_];
static __device__ float g_qb[H_ * NB_ * D_];
static __device__ float g_kb[H_ * NB_ * D_];

static __device__ __align__(16) unsigned char g_hsp[(size_t)S_ * PROW_E];
static __device__ __align__(16) unsigned char g_wqp[(size_t)E_ * PROW_E];
static __device__ __align__(16) unsigned char g_wkp[(size_t)E_ * PROW_E];
static __device__ __align__(16) unsigned char g_wvp[(size_t)E_ * PROW_E];
static __device__ __align__(16) unsigned char g_wop[(size_t)E_ * PROW_E];
static __device__ __align__(16) unsigned char g_qp [(size_t)S_ * PROW_E];
static __device__ __align__(16) unsigned char g_kp [(size_t)S_ * PROW_E];
static __device__ __align__(16) unsigned char g_vtp[(size_t)H_ * D_ * PROW_S];
static __device__ __align__(16) unsigned char g_ctxp[(size_t)S_ * PROW_E];

// ---------------- helpers ---------------------------------------------------
__device__ __forceinline__ uint32_t smem_u32(const void* p) {
    uint32_t a;
    asm("{ .reg .u64 t; cvta.to.shared.u64 t, %1; cvt.u32.u64 %0, t; }" : "=r"(a) : "l"(p));
    return a;
}

#define LDSM4(r0, r1, r2, r3, addr)                                        \
    asm volatile("ldmatrix.sync.aligned.m8n8.x4.shared.b16 {%0,%1,%2,%3}, [%4];" \
                 : "=r"(r0), "=r"(r1), "=r"(r2), "=r"(r3) : "r"(addr))

#define CP16(saddr, gptr)                                                  \
    asm volatile("cp.async.cg.shared.global [%0], [%1], 16;"               \
                 :: "r"(saddr), "l"(gptr) : "memory")
#define CP_COMMIT() asm volatile("cp.async.commit_group;" ::: "memory")
#define CP_WAIT(N)  asm volatile("cp.async.wait_group %0;" :: "n"(N) : "memory")

__device__ __forceinline__ void mma_f16(float* c, const uint32_t* a, const uint32_t* b) {
    asm volatile(
        "mma.sync.aligned.m16n8k16.row.col.f32.f16.f16.f32 "
        "{%0,%1,%2,%3}, {%4,%5,%6,%7}, {%8,%9}, {%0,%1,%2,%3};"
        : "+f"(c[0]), "+f"(c[1]), "+f"(c[2]), "+f"(c[3])
        : "r"(a[0]), "r"(a[1]), "r"(a[2]), "r"(a[3]), "r"(b[0]), "r"(b[1]));
}

// fp16 hi/lo split of two floats
__device__ __forceinline__ void split2(float x, float y, uint32_t& h, uint32_t& l) {
    __half2 hb = __floats2half2_rn(x, y);
    float rx = x - __low2float(hb);
    float ry = y - __high2float(hb);
    __half2 lb = __floats2half2_rn(rx, ry);
    h = *reinterpret_cast<uint32_t*>(&hb);
    l = *reinterpret_cast<uint32_t*>(&lb);
}

__device__ __forceinline__ uint32_t h2_of(float x, float y) {
    __half2 hb = __floats2half2_rn(x, y);
    return *reinterpret_cast<uint32_t*>(&hb);
}

__device__ __forceinline__ void pack1(unsigned char* rowbase, int col, float v, bool wlo) {
    __half hv = __float2half_rn(v);
    unsigned char* o = rowbase + (col >> 5) * 128 + (col & 31) * 2;
    *(__half*)o = hv;
    if (wlo) *(__half*)(o + 64) = __float2half_rn(v - __half2float(hv));
}

// ---------------- reductions ------------------------------------------------
__device__ __forceinline__ float blockReduceMax(float v, float* red) {
    int tid = threadIdx.x;
    red[tid] = v; __syncthreads();
    for (int s = 128; s > 0; s >>= 1) {
        if (tid < s) red[tid] = fmaxf(red[tid], red[tid + s]);
        __syncthreads();
    }
    float r = red[0]; __syncthreads();
    return r;
}
__device__ __forceinline__ float blockReduceSum(float v, float* red) {
    int tid = threadIdx.x;
    red[tid] = v; __syncthreads();
    for (int s = 128; s > 0; s >>= 1) {
        if (tid < s) red[tid] = red[tid] + red[tid + s];
        __syncthreads();
    }
    float r = red[0]; __syncthreads();
    return r;
}

// ---------------- pack fp32 -> fp16 [hi32|lo32] chunks (K = E_) -------------
__device__ __forceinline__ void pack_one(const float* __restrict__ in,
                                         unsigned char* __restrict__ out, int idx) {
    int row = idx >> 9;
    int rem = idx & 511;
    int chunk = rem >> 2, g = rem & 3;
    const float4* p = (const float4*)(in + (size_t)row * E_ + chunk * 32 + g * 8);
    float4 v0 = p[0], v1 = p[1];
    uint4 hi, lo;
    split2(v0.x, v0.y, hi.x, lo.x); split2(v0.z, v0.w, hi.y, lo.y);
    split2(v1.x, v1.y, hi.z, lo.z); split2(v1.z, v1.w, hi.w, lo.w);
    unsigned char* ob = out + (size_t)row * PROW_E + chunk * 128 + g * 16;
    *(uint4*)ob        = hi;
    *(uint4*)(ob + 64) = lo;
}

// all 5 pack jobs in ONE launch: blockIdx.y selects matrix (0=hs, 1..4=W)
__global__ void k_pack5(const float* __restrict__ hs,
                        const float* __restrict__ W0, const float* __restrict__ W1,
                        const float* __restrict__ W2, const float* __restrict__ W3,
                        unsigned char* __restrict__ Oh,
                        unsigned char* __restrict__ O0, unsigned char* __restrict__ O1,
                        unsigned char* __restrict__ O2, unsigned char* __restrict__ O3) {
    int idx = blockIdx.x * 256 + threadIdx.x;
    const float* in; unsigned char* out; int n8;
    switch (blockIdx.y) {
        case 0:  in = hs; out = Oh; n8 = S_ * E_ / 8; break;
        case 1:  in = W0; out = O0; n8 = E_ * E_ / 8; break;
        case 2:  in = W1; out = O1; n8 = E_ * E_ / 8; break;
        case 3:  in = W2; out = O2; n8 = E_ * E_ / 8; break;
        default: in = W3; out = O3; n8 = E_ * E_ / 8; break;
    }
    if (idx >= n8) return;
    pack_one(in, out, idx);
}

// ---------------- big GEMM body: fp16 2-term, cp.async 3-stage, occ 2 -------
#define GSTAGE 32768
#define GSMEM  (3 * GSTAGE)

__device__ __forceinline__ void gemm_body(const unsigned char* __restrict__ Ap,
                                          const unsigned char* __restrict__ Bp,
                                          float* __restrict__ C,
                                          unsigned char* sm) {
    const int tid  = threadIdx.x;
    const int lane = tid & 31;
    const int wid  = tid >> 5;
    const int wm   = wid & 1;
    const int wn   = wid >> 1;
    const int brow = blockIdx.y * 128;
    const int bcol = blockIdx.x * 128;
    const uint32_t sm_u = smem_u32(sm);

    float acc[4][4][4];
#pragma unroll
    for (int i = 0; i < 4; i++)
#pragma unroll
        for (int j = 0; j < 4; j++)
#pragma unroll
            for (int r = 0; r < 4; r++) acc[i][j][r] = 0.0f;

    const int lrow = tid >> 1;
    const int lsg0 = (tid & 1) * 4;
    const unsigned char* Ar = Ap + (size_t)(brow + lrow) * PROW_E + lsg0 * 16;
    const unsigned char* Br = Bp + (size_t)(bcol + lrow) * PROW_E + lsg0 * 16;

    uint32_t so[4];
#pragma unroll
    for (int i = 0; i < 4; i++)
        so[i] = (uint32_t)lrow * 128 + (((uint32_t)((lsg0 + i) * 16)) ^ ((uint32_t)(lrow & 7) << 4));

    const uint32_t swz    = (uint32_t)(lane & 7) << 4;
    const uint32_t a_part = (uint32_t)((lane >> 4) << 4);
    const uint32_t b_part = (uint32_t)(((lane >> 3) & 1) << 4);
    const uint32_t a_rowb = (uint32_t)(wm * 64 + (lane & 15)) * 128;
    const uint32_t b_rowb = (uint32_t)(wn * 32 + ((lane >> 4) << 3) + (lane & 7)) * 128;

#pragma unroll
    for (int s = 0; s < 2; s++) {
        const uint32_t st = sm_u + s * GSTAGE;
        const unsigned char* Ac = Ar + s * 128;
        const unsigned char* Bc = Br + s * 128;
#pragma unroll
        for (int i = 0; i < 4; i++) {
            CP16(st + so[i], Ac + i * 16);
            CP16(st + 16384 + so[i], Bc + i * 16);
        }
        CP_COMMIT();
    }

    const int NC = E_ / 32;          // 128
    for (int c = 0; c < NC; c++) {
        if (c + 1 < NC) { CP_WAIT(1); } else { CP_WAIT(0); }
        __syncthreads();
        if (c + 2 < NC) {
            const uint32_t st = sm_u + (uint32_t)((c + 2) % 3) * GSTAGE;
            const unsigned char* Ac = Ar + (size_t)(c + 2) * 128;
            const unsigned char* Bc = Br + (size_t)(c + 2) * 128;
#pragma unroll
            for (int i = 0; i < 4; i++) {
                CP16(st + so[i], Ac + i * 16);
                CP16(st + 16384 + so[i], Bc + i * 16);
            }
            CP_COMMIT();
        }

        const uint32_t As_u = sm_u + (uint32_t)(c % 3) * GSTAGE;
        const uint32_t Bs_u = As_u + 16384;
#pragma unroll
        for (int ks = 0; ks < 2; ks++) {
            uint32_t bh[4][2], bl[4][2];
#pragma unroll
            for (int p = 0; p < 2; p++) {
                uint32_t base = Bs_u + b_rowb + p * 2048;
                uint32_t r0, r1, r2, r3;
                LDSM4(r0, r1, r2, r3, base + ((((uint32_t)(ks << 5)) | b_part) ^ swz));
                bh[p * 2][0] = r0; bh[p * 2][1] = r1;
                bh[p * 2 + 1][0] = r2; bh[p * 2 + 1][1] = r3;
                LDSM4(r0, r1, r2, r3, base + (((64u | (uint32_t)(ks << 5)) | b_part) ^ swz));
                bl[p * 2][0] = r0; bl[p * 2][1] = r1;
                bl[p * 2 + 1][0] = r2; bl[p * 2 + 1][1] = r3;
            }
#pragma unroll
            for (int mt = 0; mt < 4; mt++) {
                uint32_t ah[4];
                uint32_t base = As_u + a_rowb + mt * 2048;
                LDSM4(ah[0], ah[1], ah[2], ah[3],
                      base + ((((uint32_t)(ks << 5)) | a_part) ^ swz));
#pragma unroll
                for (int nt = 0; nt < 4; nt++) {
                    mma_f16(acc[mt][nt], ah, bh[nt]);
                    mma_f16(acc[mt][nt], ah, bl[nt]);
                }
            }
        }
    }

    const int g = lane >> 2, tg2 = (lane & 3) * 2;
#pragma unroll
    for (int mt = 0; mt < 4; mt++) {
        int r0 = brow + wm * 64 + mt * 16 + g;
#pragma unroll
        for (int nt = 0; nt < 4; nt++) {
            int cc = bcol + wn * 32 + nt * 8 + tg2;
            *(float2*)&C[(size_t)r0 * E_ + cc]       = make_float2(acc[mt][nt][0], acc[mt][nt][1]);
            *(float2*)&C[(size_t)(r0 + 8) * E_ + cc] = make_float2(acc[mt][nt][2], acc[mt][nt][3]);
        }
    }
}

__global__ __launch_bounds__(256, 2) void k_gemm3(const unsigned char* __restrict__ Ap,
                                                  const unsigned char* __restrict__ B0,
                                                  const unsigned char* __restrict__ B1,
                                                  const unsigned char* __restrict__ B2,
                                                  float* __restrict__ C0,
                                                  float* __restrict__ C1,
                                                  float* __restrict__ C2) {
    extern __shared__ unsigned char sm[];
    const unsigned char* Bp = (blockIdx.z == 0) ? B0 : ((blockIdx.z == 1) ? B1 : B2);
    float* C = (blockIdx.z == 0) ? C0 : ((blockIdx.z == 1) ? C1 : C2);
    gemm_body(Ap, Bp, C, sm);
}

// ---------------- fp16 2-term core for attention GEMMs ----------------------
#define MMA_SMEM 65536
__device__ __forceinline__ void mma_core(const unsigned char* __restrict__ Abase, int strideA,
                                         const unsigned char* __restrict__ Bbase, int strideB,
                                         int NC, unsigned char* sm, uint32_t sm_u,
                                         float acc[4][4][4]) {
    const int tid  = threadIdx.x;
    const int lane = tid & 31;
    const int wid  = tid >> 5;
    const int wm   = wid & 1;
    const int wn   = wid >> 1;

    const int lrow = tid >> 1;
    const int lsg0 = (tid & 1) * 4;

    const uint32_t swz    = (uint32_t)(lane & 7) << 4;
    const uint32_t a_part = (uint32_t)((lane >> 4) << 4);
    const uint32_t b_part = (uint32_t)(((lane >> 3) & 1) << 4);
    const uint32_t a_rowb = (uint32_t)(wm * 64 + (lane & 15)) * 128;
    const uint32_t b_rowb = (uint32_t)(wn * 32 + ((lane >> 4) << 3) + (lane & 7)) * 128;

    const unsigned char* Ar = Abase + (size_t)lrow * strideA + lsg0 * 16;
    const unsigned char* Br = Bbase + (size_t)lrow * strideB + lsg0 * 16;

    uint32_t so[4];
#pragma unroll
    for (int i = 0; i < 4; i++)
        so[i] = (uint32_t)lrow * 128 + (((uint32_t)((lsg0 + i) * 16)) ^ ((uint32_t)(lrow & 7) << 4));

    uint4 pa[4], pb[4];
#pragma unroll
    for (int i = 0; i < 4; i++) { pa[i] = *(const uint4*)(Ar + i * 16); pb[i] = *(const uint4*)(Br + i * 16); }
#pragma unroll
    for (int i = 0; i < 4; i++) { *(uint4*)(sm + so[i]) = pa[i]; *(uint4*)(sm + 16384 + so[i]) = pb[i]; }
    __syncthreads();

    for (int c = 0; c < NC; c++) {
        if (c + 1 < NC) {
            const unsigned char* Arn = Ar + (size_t)(c + 1) * 128;
            const unsigned char* Brn = Br + (size_t)(c + 1) * 128;
#pragma unroll
            for (int i = 0; i < 4; i++) { pa[i] = *(const uint4*)(Arn + i * 16); pb[i] = *(const uint4*)(Brn + i * 16); }
        }
        const uint32_t As_u = sm_u + (uint32_t)(c & 1) * 32768;
        const uint32_t Bs_u = As_u + 16384;
#pragma unroll
        for (int ks = 0; ks < 2; ks++) {
            uint32_t bh[4][2], bl[4][2];
#pragma unroll
            for (int p = 0; p < 2; p++) {
                uint32_t base = Bs_u + b_rowb + p * 2048;
                uint32_t r0, r1, r2, r3;
                LDSM4(r0, r1, r2, r3, base + ((((uint32_t)(ks << 5)) | b_part) ^ swz));
                bh[p * 2][0] = r0; bh[p * 2][1] = r1;
                bh[p * 2 + 1][0] = r2; bh[p * 2 + 1][1] = r3;
                LDSM4(r0, r1, r2, r3, base + (((64u | (uint32_t)(ks << 5)) | b_part) ^ swz));
                bl[p * 2][0] = r0; bl[p * 2][1] = r1;
                bl[p * 2 + 1][0] = r2; bl[p * 2 + 1][1] = r3;
            }
#pragma unroll
            for (int mt = 0; mt < 4; mt++) {
                uint32_t ah[4];
                uint32_t base = As_u + a_rowb + mt * 2048;
                LDSM4(ah[0], ah[1], ah[2], ah[3],
                      base + ((((uint32_t)(ks << 5)) | a_part) ^ swz));
#pragma unroll
                for (int nt = 0; nt < 4; nt++) {
                    mma_f16(acc[mt][nt], ah, bh[nt]);
                    mma_f16(acc[mt][nt], ah, bl[nt]);
                }
            }
        }
        if (c + 1 < NC) {
            unsigned char* st = sm + ((c + 1) & 1) * 32768;
#pragma unroll
            for (int i = 0; i < 4; i++) { *(uint4*)(st + so[i]) = pa[i]; *(uint4*)(st + 16384 + so[i]) = pb[i]; }
        }
        __syncthreads();
    }
}

// ---------------- RoPE: fp32 in place + fp16 pack q(hi),k(hi+lo) ------------
__global__ void k_rope(const float* __restrict__ cosp, const float* __restrict__ sinp) {
    int idx = blockIdx.x * 256 + threadIdx.x;
    if (idx >= S_ * H_ * 64) return;
    int d = idx & 63;
    int h = (idx >> 6) & 31;
    int s = idx >> 11;
    size_t base = (size_t)s * E_ + h * D_;
    float c1 = cosp[s * D_ + d],      s1 = sinp[s * D_ + d];
    float c2 = cosp[s * D_ + d + 64], s2 = sinp[s * D_ + d + 64];
    float q1 = g_q[base + d], q2 = g_q[base + d + 64];
    float qo1 = q1 * c1 - q2 * s1;
    float qo2 = q2 * c2 + q1 * s2;
    g_q[base + d]      = qo1;
    g_q[base + d + 64] = qo2;
    float k1 = g_k[base + d], k2 = g_k[base + d + 64];
    float ko1 = k1 * c1 - k2 * s1;
    float ko2 = k2 * c2 + k1 * s2;
    g_k[base + d]      = ko1;
    g_k[base + d + 64] = ko2;
    unsigned char* rq = g_qp + (size_t)s * PROW_E;
    unsigned char* rk = g_kp + (size_t)s * PROW_E;
    pack1(rq, h * 128 + d,      qo1, false);    // q = A side: hi only
    pack1(rq, h * 128 + d + 64, qo2, false);
    pack1(rk, h * 128 + d,      ko1, true);     // k = B side: hi+lo
    pack1(rk, h * 128 + d + 64, ko2, true);
}

// ---------------- V^T pack (fp16 hi/lo; B side of ctx) ----------------------
__global__ __launch_bounds__(256) void k_packT() {
    int j0 = blockIdx.x * 64, d0 = blockIdx.y * 32, h = blockIdx.z;
    __shared__ float t[64][33];
    int tid = threadIdx.x;
    for (int u = tid; u < 64 * 32; u += 256) {
        int jj = u >> 5, dd = u & 31;
        t[jj][dd] = g_v[(size_t)(j0 + jj) * E_ + h * 128 + d0 + dd];
    }
    __syncthreads();
    for (int u = tid; u < 32 * 32; u += 256) {
        int dd = u >> 5, pr = u & 31;
        int jj = pr * 2;
        uint32_t hi, lo;
        split2(t[jj][dd], t[jj + 1][dd], hi, lo);
        unsigned char* o = g_vtp + (size_t)h * 128 * PROW_S + (size_t)(d0 + dd) * PROW_S
                         + ((j0 + jj) >> 5) * 128 + (jj & 31) * 2;
        *(uint32_t*)o        = hi;
        *(uint32_t*)(o + 64) = lo;
    }
}

// ---------------- scores: f16 MMA + mask + quadrant max ---------------------
__global__ __launch_bounds__(256, 1) void k_scores_mma() {
    const int jt = blockIdx.x, qt = blockIdx.y, h = blockIdx.z;
    if (jt > qt) return;
    extern __shared__ unsigned char sm[];
    __shared__ float qmax[8];
    float acc[4][4][4];
#pragma unroll
    for (int i = 0; i < 4; i++)
#pragma unroll
        for (int j = 0; j < 4; j++)
#pragma unroll
            for (int r = 0; r < 4; r++) acc[i][j][r] = 0.0f;

    mma_core(g_qp + (size_t)(qt * 128) * PROW_E + h * 512, PROW_E,
             g_kp + (size_t)(jt * 128) * PROW_E + h * 512, PROW_E, 4, sm, smem_u32(sm), acc);

    const int tid  = threadIdx.x;
    const int lane = tid & 31;
    const int wid  = tid >> 5;
    const int wm = wid & 1, wn = wid >> 1;
    const int g = lane >> 2, tg2 = (lane & 3) * 2;
    const float scale = 0.08838834764831845f;
    float lmax = -INFINITY;
    float* Sbase = &g_scores[(size_t)h * S_ * S_];
#pragma unroll
    for (int mt = 0; mt < 4; mt++) {
#pragma unroll
        for (int nt = 0; nt < 4; nt++) {
            int col = jt * 128 + wn * 32 + nt * 8 + tg2;
#pragma unroll
            for (int hr = 0; hr < 2; hr++) {
                int row = qt * 128 + wm * 64 + mt * 16 + g + hr * 8;
                float v0 = acc[mt][nt][hr * 2 + 0] * scale;
                float v1 = acc[mt][nt][hr * 2 + 1] * scale;
                if (col > row)     v0 = -INFINITY;
                if (col + 1 > row) v1 = -INFINITY;
                *(float2*)&Sbase[(size_t)row * S_ + col] = make_float2(v0, v1);
                lmax = fmaxf(lmax, fmaxf(v0, v1));
            }
        }
    }
#pragma unroll
    for (int off = 16; off > 0; off >>= 1)
        lmax = fmaxf(lmax, __shfl_xor_sync(0xFFFFFFFFu, lmax, off));
    if (lane == 0) qmax[wid] = lmax;
    __syncthreads();
    if (tid < 4) {
        int qr = tid & 1, qc = tid >> 1;
        float m = fmaxf(qmax[qr | (qc << 2)], qmax[qr | (qc << 2) | 2]);
        g_bmax[h * 1024 + (qt * 2 + qr) * 32 + (jt * 2 + qc)] = m;
    }
}

// ---------------- row softmax: fp32 -> packed fp16 hi-only probs ------------
__global__ __launch_bounds__(256) void k_softmax() {
    const int i = blockIdx.x, h = blockIdx.y;
    __shared__ float row[S_];
    __shared__ float red[256];
    const int tid = threadIdx.x;
    const int len = i + 1;
    size_t base = (size_t)h * S_ * S_ + (size_t)i * S_;
    float m = -INFINITY;
    for (int j = tid; j < len; j += 256) {
        float v = g_scores[base + j];
        row[j] = v;
        m = fmaxf(m, v);
    }
    float mx = blockReduceMax(m, red);
    float sum = 0.0f;
    for (int j = tid; j < len; j += 256) {
        float p = expf(row[j] - mx);
        row[j] = p;
        sum += p;
    }
    float s = blockReduceSum(sum, red);
    float inv = 1.0f / s;
    const int padlen = ((i >> 7) + 1) << 7;
    unsigned char* rowp = (unsigned char*)&g_scores[base];
    for (int jj = tid * 2; jj < padlen; jj += 512) {
        float p0 = (jj     < len) ? row[jj]     * inv : 0.0f;
        float p1 = (jj + 1 < len) ? row[jj + 1] * inv : 0.0f;
        unsigned char* o = rowp + (jj >> 5) * 128 + (jj & 31) * 2;
        *(uint32_t*)o = h2_of(p0, p1);     // hi only; lo never read (A side)
    }
}

// ---------------- ctx: f16 MMA P@V^T -> packed ctx (hi only) ----------------
__global__ __launch_bounds__(256, 1) void k_ctx_mma() {
    const int qt = 15 - blockIdx.x;
    const int h  = blockIdx.y;
    extern __shared__ unsigned char sm[];
    float acc[4][4][4];
#pragma unroll
    for (int i = 0; i < 4; i++)
#pragma unroll
        for (int j = 0; j < 4; j++)
#pragma unroll
            for (int r = 0; r < 4; r++) acc[i][j][r] = 0.0f;

    mma_core((const unsigned char*)g_scores + (size_t)h * S_ * S_ * 4 + (size_t)(qt * 128) * PROW_S, PROW_S,
             g_vtp + (size_t)h * 128 * PROW_S, PROW_S, (qt + 1) * 4, sm, smem_u32(sm), acc);

    const int lane = threadIdx.x & 31;
    const int wid  = threadIdx.x >> 5;
    const int wm = wid & 1, wn = wid >> 1;
    const int g = lane >> 2, tg2 = (lane & 3) * 2;
#pragma unroll
    for (int mt = 0; mt < 4; mt++) {
#pragma unroll
        for (int nt = 0; nt < 4; nt++) {
            int colg = h * 128 + wn * 32 + nt * 8 + tg2;
            int coff = (colg >> 5) * 128 + (colg & 31) * 2;
#pragma unroll
            for (int hr = 0; hr < 2; hr++) {
                int row = qt * 128 + wm * 64 + mt * 16 + g + hr * 8;
                unsigned char* o = g_ctxp + (size_t)row * PROW_E + coff;
                *(uint32_t*)o = h2_of(acc[mt][nt][hr * 2 + 0], acc[mt][nt][hr * 2 + 1]);
            }
        }
    }
}

// ---------------- block means of post-RoPE q, k -----------------------------
__global__ void k_blockmean() {
    int idx = blockIdx.x * 256 + threadIdx.x;
    if (idx >= H_ * NB_ * D_) return;
    int d  = idx & 127;
    int nb = (idx >> 7) & 31;
    int h  = idx >> 12;
    float sq = 0.0f, sk = 0.0f;
    for (int r = 0; r < 64; r++) {
        size_t o = (size_t)(nb * 64 + r) * E_ + h * D_ + d;
        sq += g_q[o];
        sk += g_k[o];
    }
    g_qb[idx] = sq * (1.0f / 64.0f);
    g_kb[idx] = sk * (1.0f / 64.0f);
}

// ---------------- gate_pred --------------------------------------------------
__global__ __launch_bounds__(256) void k_gatepred(const float* __restrict__ Wgq,
                                                  const float* __restrict__ Wgk,
                                                  float* __restrict__ out) {
    const int h = blockIdx.x, tid = threadIdx.x;
    __shared__ float sgq[32 * 64];
    __shared__ float sgk[32 * 64];
    __shared__ float slog[1024];
    __shared__ float red[256];
    for (int t = tid; t < 2048; t += 256) {
        int nb = t >> 6, g = t & 63;
        float aq = 0.0f, ak = 0.0f;
        const float* qb = &g_qb[h * 4096 + nb * 128];
        const float* kb = &g_kb[h * 4096 + nb * 128];
        const float* w1 = &Wgq[g * 128];
        const float* w2 = &Wgk[g * 128];
#pragma unroll 4
        for (int d = 0; d < 128; d++) {
            aq = fmaf(qb[d], w1[d], aq);
            ak = fmaf(kb[d], w2[d], ak);
        }
        sgq[nb * 64 + g] = aq;
        sgk[nb * 64 + g] = ak;
    }
    __syncthreads();
    for (int t = tid; t < 1024; t += 256) {
        int nq = t >> 5, nk = t & 31;
        float v;
        if (nk <= nq) {
            v = 0.0f;
#pragma unroll 8
            for (int g = 0; g < 64; g++) v = fmaf(sgq[nq * 64 + g], sgk[nk * 64 + g], v);
            v *= 0.125f;
        } else {
            v = -INFINITY;
        }
        slog[t] = v;
    }
    __syncthreads();
    float m = -INFINITY;
    for (int t = tid; t < 1024; t += 256) m = fmaxf(m, slog[t]);
    float mx = blockReduceMax(m, red);
    float sum = 0.0f;
    for (int t = tid; t < 1024; t += 256) {
        float p = expf(slog[t] - mx);
        slog[t] = p;
        sum += p;
    }
    float s = blockReduceSum(sum, red);
    float inv = 1.0f / s;
    for (int t = tid; t < 1024; t += 256) out[h * 1024 + t] = slog[t] * inv;
}

// ---------------- gate_target ------------------------------------------------
__global__ __launch_bounds__(256) void k_gatetarget(float* __restrict__ out) {
    const int h = blockIdx.x, tid = threadIdx.x;
    __shared__ float sx[1024];
    __shared__ float red[256];
    for (int t = tid; t < 1024; t += 256) {
        int nq = t >> 5, nk = t & 31;
        float v;
        if (nk <= nq) {
            v = g_bmax[h * 1024 + t];
            v = fminf(fmaxf(v, -50.0f), 50.0f);
            v *= 0.5f;
        } else {
            v = -INFINITY;
        }
        sx[t] = v;
    }
    __syncthreads();
    float m = -INFINITY;
    for (int t = tid; t < 1024; t += 256) m = fmaxf(m, sx[t]);
    float mx = blockReduceMax(m, red);
    float sum = 0.0f;
    for (int t = tid; t < 1024; t += 256) {
        float p = expf(sx[t] - mx);
        sx[t] = p;
        sum += p;
    }
    float s = blockReduceSum(sum, red);
    float inv = 1.0f / s;
    for (int t = tid; t < 1024; t += 256) out[h * 1024 + t] = sx[t] * inv;
}

// ---------------- launch ------------------------------------------------------
extern "C" void kernel_launch(void* const* d_in, const int* in_sizes, int n_in,
                              void* d_out, int out_size) {
    const float* hs   = (const float*)d_in[0];
    const float* cosp = (const float*)d_in[1];
    const float* sinp = (const float*)d_in[2];
    const float* Wq   = (const float*)d_in[3];
    const float* Wk   = (const float*)d_in[4];
    const float* Wv   = (const float*)d_in[5];
    const float* Wo   = (const float*)d_in[6];
    const float* Wgq  = (const float*)d_in[7];
    const float* Wgk  = (const float*)d_in[8];
    float* out = (float*)d_out;

    const int GP_OFF = S_ * E_;
    const int GT_OFF = GP_OFF + H_ * NB_ * NB_;

    cudaFuncSetAttribute(k_gemm3,      cudaFuncAttributeMaxDynamicSharedMemorySize, GSMEM);
    cudaFuncSetAttribute(k_scores_mma, cudaFuncAttributeMaxDynamicSharedMemorySize, MMA_SMEM);
    cudaFuncSetAttribute(k_ctx_mma,    cudaFuncAttributeMaxDynamicSharedMemorySize, MMA_SMEM);

    unsigned char *hsp, *wqp, *wkp, *wvp, *wop, *ctxp;
    float *qf, *kf, *vf;
    cudaGetSymbolAddress((void**)&hsp,  g_hsp);
    cudaGetSymbolAddress((void**)&wqp,  g_wqp);
    cudaGetSymbolAddress((void**)&wkp,  g_wkp);
    cudaGetSymbolAddress((void**)&wvp,  g_wvp);
    cudaGetSymbolAddress((void**)&wop,  g_wop);
    cudaGetSymbolAddress((void**)&ctxp, g_ctxp);
    cudaGetSymbolAddress((void**)&qf,   g_q);
    cudaGetSymbolAddress((void**)&kf,   g_k);
    cudaGetSymbolAddress((void**)&vf,   g_v);

    const int n8_w = E_ * E_ / 8;
    k_pack5<<<dim3((n8_w + 255) / 256, 5), 256>>>(hs, Wq, Wk, Wv, Wo,
                                                  hsp, wqp, wkp, wvp, wop);

    dim3 ggrid3(E_ / 128, S_ / 128, 3);
    k_gemm3<<<ggrid3, 256, GSMEM>>>(hsp, wqp, wkp, wvp, qf, kf, vf);

    k_rope<<<(S_ * H_ * 64 + 255) / 256, 256>>>(cosp, sinp);
    k_packT<<<dim3(S_ / 64, D_ / 32, H_), 256>>>();

    k_scores_mma<<<dim3(16, 16, H_), 256, MMA_SMEM>>>();
    k_softmax<<<dim3(S_, H_), 256>>>();
    k_ctx_mma<<<dim3(16, H_), 256, MMA_SMEM>>>();

    dim3 ggrid1(E_ / 128, S_ / 128, 1);
    k_gemm3<<<ggrid1, 256, GSMEM>>>(ctxp, wop, wop, wop, out, out, out);

    k_blockmean<<<(H_ * NB_ * D_ + 255) / 256, 256>>>();
    k_gatepred<<<H_, 256>>>(Wgq, Wgk, out + GP_OFF);
    k_gatetarget<<<H_, 256>>>(out + GT_OFF);
}

// round 16
// speedup vs baseline: 1.5277x; 1.5277x over previous
#include <cuda_runtime.h>
#include <cuda_fp16.h>
#include <math.h>
#include <stdint.h>

#define S_  2048
#define E_  4096
#define H_  32
#define D_  128
#define NB_ 32
#define BS_ 64

// packed fp16 hi/lo row strides (bytes): K elems -> (K/32) chunks of 128B [hi64|lo64]
#define PROW_E 16384      // K = 4096
#define PROW_S 8192       // K = 2048

// ---------------- scratch ---------------------------------------------------
static __device__ float g_q[(size_t)S_ * E_];
static __device__ float g_k[(size_t)S_ * E_];
static __device__ float g_v[(size_t)S_ * E_];
static __device__ float g_scores[(size_t)H_ * S_ * S_];
static __device__ float g_bmax[H_ * NB_ * NB_];
static __device__ float g_qb[H_ * NB_ * D_];
static __device__ float g_kb[H_ * NB_ * D_];

static __device__ __align__(16) unsigned char g_hsp[(size_t)S_ * PROW_E];
static __device__ __align__(16) unsigned char g_wqp[(size_t)E_ * PROW_E];
static __device__ __align__(16) unsigned char g_wkp[(size_t)E_ * PROW_E];
static __device__ __align__(16) unsigned char g_wvp[(size_t)E_ * PROW_E];
static __device__ __align__(16) unsigned char g_wop[(size_t)E_ * PROW_E];
static __device__ __align__(16) unsigned char g_qp [(size_t)S_ * PROW_E];
static __device__ __align__(16) unsigned char g_kp [(size_t)S_ * PROW_E];
static __device__ __align__(16) unsigned char g_vtp[(size_t)H_ * D_ * PROW_S];
static __device__ __align__(16) unsigned char g_ctxp[(size_t)S_ * PROW_E];

// ---------------- helpers ---------------------------------------------------
__device__ __forceinline__ uint32_t smem_u32(const void* p) {
    uint32_t a;
    asm("{ .reg .u64 t; cvta.to.shared.u64 t, %1; cvt.u32.u64 %0, t; }" : "=r"(a) : "l"(p));
    return a;
}

#define LDSM4(r0, r1, r2, r3, addr)                                        \
    asm volatile("ldmatrix.sync.aligned.m8n8.x4.shared.b16 {%0,%1,%2,%3}, [%4];" \
                 : "=r"(r0), "=r"(r1), "=r"(r2), "=r"(r3) : "r"(addr))

#define CP16(saddr, gptr)                                                  \
    asm volatile("cp.async.cg.shared.global [%0], [%1], 16;"               \
                 :: "r"(saddr), "l"(gptr) : "memory")
#define CP_COMMIT() asm volatile("cp.async.commit_group;" ::: "memory")
#define CP_WAIT(N)  asm volatile("cp.async.wait_group %0;" :: "n"(N) : "memory")

__device__ __forceinline__ void mma_f16(float* c, const uint32_t* a, const uint32_t* b) {
    asm volatile(
        "mma.sync.aligned.m16n8k16.row.col.f32.f16.f16.f32 "
        "{%0,%1,%2,%3}, {%4,%5,%6,%7}, {%8,%9}, {%0,%1,%2,%3};"
        : "+f"(c[0]), "+f"(c[1]), "+f"(c[2]), "+f"(c[3])
        : "r"(a[0]), "r"(a[1]), "r"(a[2]), "r"(a[3]), "r"(b[0]), "r"(b[1]));
}

// fp16 hi/lo split of two floats
__device__ __forceinline__ void split2(float x, float y, uint32_t& h, uint32_t& l) {
    __half2 hb = __floats2half2_rn(x, y);
    float rx = x - __low2float(hb);
    float ry = y - __high2float(hb);
    __half2 lb = __floats2half2_rn(rx, ry);
    h = *reinterpret_cast<uint32_t*>(&hb);
    l = *reinterpret_cast<uint32_t*>(&lb);
}

__device__ __forceinline__ uint32_t h2_of(float x, float y) {
    __half2 hb = __floats2half2_rn(x, y);
    return *reinterpret_cast<uint32_t*>(&hb);
}

__device__ __forceinline__ void pack1(unsigned char* rowbase, int col, float v, bool wlo) {
    __half hv = __float2half_rn(v);
    unsigned char* o = rowbase + (col >> 5) * 128 + (col & 31) * 2;
    *(__half*)o = hv;
    if (wlo) *(__half*)(o + 64) = __float2half_rn(v - __half2float(hv));
}

// ---------------- reductions ------------------------------------------------
__device__ __forceinline__ float blockReduceMax(float v, float* red) {
    int tid = threadIdx.x;
    red[tid] = v; __syncthreads();
    for (int s = 128; s > 0; s >>= 1) {
        if (tid < s) red[tid] = fmaxf(red[tid], red[tid + s]);
        __syncthreads();
    }
    float r = red[0]; __syncthreads();
    return r;
}
__device__ __forceinline__ float blockReduceSum(float v, float* red) {
    int tid = threadIdx.x;
    red[tid] = v; __syncthreads();
    for (int s = 128; s > 0; s >>= 1) {
        if (tid < s) red[tid] = red[tid] + red[tid + s];
        __syncthreads();
    }
    float r = red[0]; __syncthreads();
    return r;
}

// ---------------- pack fp32 -> fp16 [hi32|lo32] chunks (K = E_) -------------
__device__ __forceinline__ void pack_one(const float* __restrict__ in,
                                         unsigned char* __restrict__ out, int idx) {
    int row = idx >> 9;
    int rem = idx & 511;
    int chunk = rem >> 2, g = rem & 3;
    const float4* p = (const float4*)(in + (size_t)row * E_ + chunk * 32 + g * 8);
    float4 v0 = p[0], v1 = p[1];
    uint4 hi, lo;
    split2(v0.x, v0.y, hi.x, lo.x); split2(v0.z, v0.w, hi.y, lo.y);
    split2(v1.x, v1.y, hi.z, lo.z); split2(v1.z, v1.w, hi.w, lo.w);
    unsigned char* ob = out + (size_t)row * PROW_E + chunk * 128 + g * 16;
    *(uint4*)ob        = hi;
    *(uint4*)(ob + 64) = lo;
}

__global__ void k_pack(const float* __restrict__ in, unsigned char* __restrict__ out,
                       int n8) {
    int idx = blockIdx.x * 256 + threadIdx.x;
    if (idx >= n8) return;
    pack_one(in, out, idx);
}

__global__ void k_packw(const float* __restrict__ W0, const float* __restrict__ W1,
                        const float* __restrict__ W2, const float* __restrict__ W3,
                        unsigned char* __restrict__ O0, unsigned char* __restrict__ O1,
                        unsigned char* __restrict__ O2, unsigned char* __restrict__ O3,
                        int n8) {
    int idx = blockIdx.x * 256 + threadIdx.x;
    if (idx >= n8) return;
    const float* in; unsigned char* out;
    switch (blockIdx.y) {
        case 0:  in = W0; out = O0; break;
        case 1:  in = W1; out = O1; break;
        case 2:  in = W2; out = O2; break;
        default: in = W3; out = O3; break;
    }
    pack_one(in, out, idx);
}

// ---------------- big GEMM body: fp16 2-term, cp.async 3-stage, occ 2 -------
#define GSTAGE 32768
#define GSMEM  (3 * GSTAGE)

__device__ __forceinline__ void gemm_body(const unsigned char* __restrict__ Ap,
                                          const unsigned char* __restrict__ Bp,
                                          float* __restrict__ C,
                                          unsigned char* sm) {
    const int tid  = threadIdx.x;
    const int lane = tid & 31;
    const int wid  = tid >> 5;
    const int wm   = wid & 1;
    const int wn   = wid >> 1;
    const int brow = blockIdx.y * 128;
    const int bcol = blockIdx.x * 128;
    const uint32_t sm_u = smem_u32(sm);

    float acc[4][4][4];
#pragma unroll
    for (int i = 0; i < 4; i++)
#pragma unroll
        for (int j = 0; j < 4; j++)
#pragma unroll
            for (int r = 0; r < 4; r++) acc[i][j][r] = 0.0f;

    const int lrow = tid >> 1;
    const int lsg0 = (tid & 1) * 4;
    const unsigned char* Ar = Ap + (size_t)(brow + lrow) * PROW_E + lsg0 * 16;
    const unsigned char* Br = Bp + (size_t)(bcol + lrow) * PROW_E + lsg0 * 16;

    uint32_t so[4];
#pragma unroll
    for (int i = 0; i < 4; i++)
        so[i] = (uint32_t)lrow * 128 + (((uint32_t)((lsg0 + i) * 16)) ^ ((uint32_t)(lrow & 7) << 4));

    const uint32_t swz    = (uint32_t)(lane & 7) << 4;
    const uint32_t a_part = (uint32_t)((lane >> 4) << 4);
    const uint32_t b_part = (uint32_t)(((lane >> 3) & 1) << 4);
    const uint32_t a_rowb = (uint32_t)(wm * 64 + (lane & 15)) * 128;
    const uint32_t b_rowb = (uint32_t)(wn * 32 + ((lane >> 4) << 3) + (lane & 7)) * 128;

#pragma unroll
    for (int s = 0; s < 2; s++) {
        const uint32_t st = sm_u + s * GSTAGE;
        const unsigned char* Ac = Ar + s * 128;
        const unsigned char* Bc = Br + s * 128;
#pragma unroll
        for (int i = 0; i < 4; i++) {
            CP16(st + so[i], Ac + i * 16);
            CP16(st + 16384 + so[i], Bc + i * 16);
        }
        CP_COMMIT();
    }

    const int NC = E_ / 32;          // 128
    for (int c = 0; c < NC; c++) {
        if (c + 1 < NC) { CP_WAIT(1); } else { CP_WAIT(0); }
        __syncthreads();
        if (c + 2 < NC) {
            const uint32_t st = sm_u + (uint32_t)((c + 2) % 3) * GSTAGE;
            const unsigned char* Ac = Ar + (size_t)(c + 2) * 128;
            const unsigned char* Bc = Br + (size_t)(c + 2) * 128;
#pragma unroll
            for (int i = 0; i < 4; i++) {
                CP16(st + so[i], Ac + i * 16);
                CP16(st + 16384 + so[i], Bc + i * 16);
            }
            CP_COMMIT();
        }

        const uint32_t As_u = sm_u + (uint32_t)(c % 3) * GSTAGE;
        const uint32_t Bs_u = As_u + 16384;
#pragma unroll
        for (int ks = 0; ks < 2; ks++) {
            uint32_t bh[4][2], bl[4][2];
#pragma unroll
            for (int p = 0; p < 2; p++) {
                uint32_t base = Bs_u + b_rowb + p * 2048;
                uint32_t r0, r1, r2, r3;
                LDSM4(r0, r1, r2, r3, base + ((((uint32_t)(ks << 5)) | b_part) ^ swz));
                bh[p * 2][0] = r0; bh[p * 2][1] = r1;
                bh[p * 2 + 1][0] = r2; bh[p * 2 + 1][1] = r3;
                LDSM4(r0, r1, r2, r3, base + (((64u | (uint32_t)(ks << 5)) | b_part) ^ swz));
                bl[p * 2][0] = r0; bl[p * 2][1] = r1;
                bl[p * 2 + 1][0] = r2; bl[p * 2 + 1][1] = r3;
            }
#pragma unroll
            for (int mt = 0; mt < 4; mt++) {
                uint32_t ah[4];
                uint32_t base = As_u + a_rowb + mt * 2048;
                LDSM4(ah[0], ah[1], ah[2], ah[3],
                      base + ((((uint32_t)(ks << 5)) | a_part) ^ swz));
#pragma unroll
                for (int nt = 0; nt < 4; nt++) {
                    mma_f16(acc[mt][nt], ah, bh[nt]);
                    mma_f16(acc[mt][nt], ah, bl[nt]);
                }
            }
        }
    }

    const int g = lane >> 2, tg2 = (lane & 3) * 2;
#pragma unroll
    for (int mt = 0; mt < 4; mt++) {
        int r0 = brow + wm * 64 + mt * 16 + g;
#pragma unroll
        for (int nt = 0; nt < 4; nt++) {
            int cc = bcol + wn * 32 + nt * 8 + tg2;
            *(float2*)&C[(size_t)r0 * E_ + cc]       = make_float2(acc[mt][nt][0], acc[mt][nt][1]);
            *(float2*)&C[(size_t)(r0 + 8) * E_ + cc] = make_float2(acc[mt][nt][2], acc[mt][nt][3]);
        }
    }
}

__global__ __launch_bounds__(256, 2) void k_gemm3(const unsigned char* __restrict__ Ap,
                                                  const unsigned char* __restrict__ B0,
                                                  const unsigned char* __restrict__ B1,
                                                  const unsigned char* __restrict__ B2,
                                                  float* __restrict__ C0,
                                                  float* __restrict__ C1,
                                                  float* __restrict__ C2) {
    extern __shared__ unsigned char sm[];
    const unsigned char* Bp = (blockIdx.z == 0) ? B0 : ((blockIdx.z == 1) ? B1 : B2);
    float* C = (blockIdx.z == 0) ? C0 : ((blockIdx.z == 1) ? C1 : C2);
    gemm_body(Ap, Bp, C, sm);
}

// ---------------- fp16 2-term core for attention GEMMs ----------------------
#define MMA_SMEM 65536
__device__ __forceinline__ void mma_core(const unsigned char* __restrict__ Abase, int strideA,
                                         const unsigned char* __restrict__ Bbase, int strideB,
                                         int NC, unsigned char* sm, uint32_t sm_u,
                                         float acc[4][4][4]) {
    const int tid  = threadIdx.x;
    const int lane = tid & 31;
    const int wid  = tid >> 5;
    const int wm   = wid & 1;
    const int wn   = wid >> 1;

    const int lrow = tid >> 1;
    const int lsg0 = (tid & 1) * 4;

    const uint32_t swz    = (uint32_t)(lane & 7) << 4;
    const uint32_t a_part = (uint32_t)((lane >> 4) << 4);
    const uint32_t b_part = (uint32_t)(((lane >> 3) & 1) << 4);
    const uint32_t a_rowb = (uint32_t)(wm * 64 + (lane & 15)) * 128;
    const uint32_t b_rowb = (uint32_t)(wn * 32 + ((lane >> 4) << 3) + (lane & 7)) * 128;

    const unsigned char* Ar = Abase + (size_t)lrow * strideA + lsg0 * 16;
    const unsigned char* Br = Bbase + (size_t)lrow * strideB + lsg0 * 16;

    uint32_t so[4];
#pragma unroll
    for (int i = 0; i < 4; i++)
        so[i] = (uint32_t)lrow * 128 + (((uint32_t)((lsg0 + i) * 16)) ^ ((uint32_t)(lrow & 7) << 4));

    uint4 pa[4], pb[4];
#pragma unroll
    for (int i = 0; i < 4; i++) { pa[i] = *(const uint4*)(Ar + i * 16); pb[i] = *(const uint4*)(Br + i * 16); }
#pragma unroll
    for (int i = 0; i < 4; i++) { *(uint4*)(sm + so[i]) = pa[i]; *(uint4*)(sm + 16384 + so[i]) = pb[i]; }
    __syncthreads();

    for (int c = 0; c < NC; c++) {
        if (c + 1 < NC) {
            const unsigned char* Arn = Ar + (size_t)(c + 1) * 128;
            const unsigned char* Brn = Br + (size_t)(c + 1) * 128;
#pragma unroll
            for (int i = 0; i < 4; i++) { pa[i] = *(const uint4*)(Arn + i * 16); pb[i] = *(const uint4*)(Brn + i * 16); }
        }
        const uint32_t As_u = sm_u + (uint32_t)(c & 1) * 32768;
        const uint32_t Bs_u = As_u + 16384;
#pragma unroll
        for (int ks = 0; ks < 2; ks++) {
            uint32_t bh[4][2], bl[4][2];
#pragma unroll
            for (int p = 0; p < 2; p++) {
                uint32_t base = Bs_u + b_rowb + p * 2048;
                uint32_t r0, r1, r2, r3;
                LDSM4(r0, r1, r2, r3, base + ((((uint32_t)(ks << 5)) | b_part) ^ swz));
                bh[p * 2][0] = r0; bh[p * 2][1] = r1;
                bh[p * 2 + 1][0] = r2; bh[p * 2 + 1][1] = r3;
                LDSM4(r0, r1, r2, r3, base + (((64u | (uint32_t)(ks << 5)) | b_part) ^ swz));
                bl[p * 2][0] = r0; bl[p * 2][1] = r1;
                bl[p * 2 + 1][0] = r2; bl[p * 2 + 1][1] = r3;
            }
#pragma unroll
            for (int mt = 0; mt < 4; mt++) {
                uint32_t ah[4];
                uint32_t base = As_u + a_rowb + mt * 2048;
                LDSM4(ah[0], ah[1], ah[2], ah[3],
                      base + ((((uint32_t)(ks << 5)) | a_part) ^ swz));
#pragma unroll
                for (int nt = 0; nt < 4; nt++) {
                    mma_f16(acc[mt][nt], ah, bh[nt]);
                    mma_f16(acc[mt][nt], ah, bl[nt]);
                }
            }
        }
        if (c + 1 < NC) {
            unsigned char* st = sm + ((c + 1) & 1) * 32768;
#pragma unroll
            for (int i = 0; i < 4; i++) { *(uint4*)(st + so[i]) = pa[i]; *(uint4*)(st + 16384 + so[i]) = pb[i]; }
        }
        __syncthreads();
    }
}

// ---------------- RoPE: fp32 in place + fp16 pack q(hi),k(hi+lo) ------------
__global__ void k_rope(const float* __restrict__ cosp, const float* __restrict__ sinp) {
    int idx = blockIdx.x * 256 + threadIdx.x;
    if (idx >= S_ * H_ * 64) return;
    int d = idx & 63;
    int h = (idx >> 6) & 31;
    int s = idx >> 11;
    size_t base = (size_t)s * E_ + h * D_;
    float c1 = cosp[s * D_ + d],      s1 = sinp[s * D_ + d];
    float c2 = cosp[s * D_ + d + 64], s2 = sinp[s * D_ + d + 64];
    float q1 = g_q[base + d], q2 = g_q[base + d + 64];
    float qo1 = q1 * c1 - q2 * s1;
    float qo2 = q2 * c2 + q1 * s2;
    g_q[base + d]      = qo1;
    g_q[base + d + 64] = qo2;
    float k1 = g_k[base + d], k2 = g_k[base + d + 64];
    float ko1 = k1 * c1 - k2 * s1;
    float ko2 = k2 * c2 + k1 * s2;
    g_k[base + d]      = ko1;
    g_k[base + d + 64] = ko2;
    unsigned char* rq = g_qp + (size_t)s * PROW_E;
    unsigned char* rk = g_kp + (size_t)s * PROW_E;
    pack1(rq, h * 128 + d,      qo1, false);    // q = A side: hi only
    pack1(rq, h * 128 + d + 64, qo2, false);
    pack1(rk, h * 128 + d,      ko1, true);     // k = B side: hi+lo
    pack1(rk, h * 128 + d + 64, ko2, true);
}

// ---------------- V^T pack (fp16 hi/lo; B side of ctx) ----------------------
__global__ __launch_bounds__(256) void k_packT() {
    int j0 = blockIdx.x * 64, d0 = blockIdx.y * 32, h = blockIdx.z;
    __shared__ float t[64][33];
    int tid = threadIdx.x;
    for (int u = tid; u < 64 * 32; u += 256) {
        int jj = u >> 5, dd = u & 31;
        t[jj][dd] = g_v[(size_t)(j0 + jj) * E_ + h * 128 + d0 + dd];
    }
    __syncthreads();
    for (int u = tid; u < 32 * 32; u += 256) {
        int dd = u >> 5, pr = u & 31;
        int jj = pr * 2;
        uint32_t hi, lo;
        split2(t[jj][dd], t[jj + 1][dd], hi, lo);
        unsigned char* o = g_vtp + (size_t)h * 128 * PROW_S + (size_t)(d0 + dd) * PROW_S
                         + ((j0 + jj) >> 5) * 128 + (jj & 31) * 2;
        *(uint32_t*)o        = hi;
        *(uint32_t*)(o + 64) = lo;
    }
}

// ---------------- scores: f16 MMA + mask + quadrant max ---------------------
__global__ __launch_bounds__(256, 1) void k_scores_mma() {
    const int jt = blockIdx.x, qt = blockIdx.y, h = blockIdx.z;
    if (jt > qt) return;
    extern __shared__ unsigned char sm[];
    __shared__ float qmax[8];
    float acc[4][4][4];
#pragma unroll
    for (int i = 0; i < 4; i++)
#pragma unroll
        for (int j = 0; j < 4; j++)
#pragma unroll
            for (int r = 0; r < 4; r++) acc[i][j][r] = 0.0f;

    mma_core(g_qp + (size_t)(qt * 128) * PROW_E + h * 512, PROW_E,
             g_kp + (size_t)(jt * 128) * PROW_E + h * 512, PROW_E, 4, sm, smem_u32(sm), acc);

    const int tid  = threadIdx.x;
    const int lane = tid & 31;
    const int wid  = tid >> 5;
    const int wm = wid & 1, wn = wid >> 1;
    const int g = lane >> 2, tg2 = (lane & 3) * 2;
    const float scale = 0.08838834764831845f;
    float lmax = -INFINITY;
    float* Sbase = &g_scores[(size_t)h * S_ * S_];
#pragma unroll
    for (int mt = 0; mt < 4; mt++) {
#pragma unroll
        for (int nt = 0; nt < 4; nt++) {
            int col = jt * 128 + wn * 32 + nt * 8 + tg2;
#pragma unroll
            for (int hr = 0; hr < 2; hr++) {
                int row = qt * 128 + wm * 64 + mt * 16 + g + hr * 8;
                float v0 = acc[mt][nt][hr * 2 + 0] * scale;
                float v1 = acc[mt][nt][hr * 2 + 1] * scale;
                if (col > row)     v0 = -INFINITY;
                if (col + 1 > row) v1 = -INFINITY;
                *(float2*)&Sbase[(size_t)row * S_ + col] = make_float2(v0, v1);
                lmax = fmaxf(lmax, fmaxf(v0, v1));
            }
        }
    }
#pragma unroll
    for (int off = 16; off > 0; off >>= 1)
        lmax = fmaxf(lmax, __shfl_xor_sync(0xFFFFFFFFu, lmax, off));
    if (lane == 0) qmax[wid] = lmax;
    __syncthreads();
    if (tid < 4) {
        int qr = tid & 1, qc = tid >> 1;
        float m = fmaxf(qmax[qr | (qc << 2)], qmax[qr | (qc << 2) | 2]);
        g_bmax[h * 1024 + (qt * 2 + qr) * 32 + (jt * 2 + qc)] = m;
    }
}

// ---------------- row softmax: fp32 -> packed fp16 hi-only probs ------------
__global__ __launch_bounds__(256) void k_softmax() {
    const int i = blockIdx.x, h = blockIdx.y;
    __shared__ float row[S_];
    __shared__ float red[256];
    const int tid = threadIdx.x;
    const int len = i + 1;
    size_t base = (size_t)h * S_ * S_ + (size_t)i * S_;
    float m = -INFINITY;
    for (int j = tid; j < len; j += 256) {
        float v = g_scores[base + j];
        row[j] = v;
        m = fmaxf(m, v);
    }
    float mx = blockReduceMax(m, red);
    float sum = 0.0f;
    for (int j = tid; j < len; j += 256) {
        float p = expf(row[j] - mx);
        row[j] = p;
        sum += p;
    }
    float s = blockReduceSum(sum, red);
    float inv = 1.0f / s;
    const int padlen = ((i >> 7) + 1) << 7;
    unsigned char* rowp = (unsigned char*)&g_scores[base];
    for (int jj = tid * 2; jj < padlen; jj += 512) {
        float p0 = (jj     < len) ? row[jj]     * inv : 0.0f;
        float p1 = (jj + 1 < len) ? row[jj + 1] * inv : 0.0f;
        unsigned char* o = rowp + (jj >> 5) * 128 + (jj & 31) * 2;
        *(uint32_t*)o = h2_of(p0, p1);     // hi only; lo never read (A side)
    }
}

// ---------------- ctx: f16 MMA P@V^T -> packed ctx (hi only) ----------------
__global__ __launch_bounds__(256, 1) void k_ctx_mma() {
    const int qt = 15 - blockIdx.x;
    const int h  = blockIdx.y;
    extern __shared__ unsigned char sm[];
    float acc[4][4][4];
#pragma unroll
    for (int i = 0; i < 4; i++)
#pragma unroll
        for (int j = 0; j < 4; j++)
#pragma unroll
            for (int r = 0; r < 4; r++) acc[i][j][r] = 0.0f;

    mma_core((const unsigned char*)g_scores + (size_t)h * S_ * S_ * 4 + (size_t)(qt * 128) * PROW_S, PROW_S,
             g_vtp + (size_t)h * 128 * PROW_S, PROW_S, (qt + 1) * 4, sm, smem_u32(sm), acc);

    const int lane = threadIdx.x & 31;
    const int wid  = threadIdx.x >> 5;
    const int wm = wid & 1, wn = wid >> 1;
    const int g = lane >> 2, tg2 = (lane & 3) * 2;
#pragma unroll
    for (int mt = 0; mt < 4; mt++) {
#pragma unroll
        for (int nt = 0; nt < 4; nt++) {
            int colg = h * 128 + wn * 32 + nt * 8 + tg2;
            int coff = (colg >> 5) * 128 + (colg & 31) * 2;
#pragma unroll
            for (int hr = 0; hr < 2; hr++) {
                int row = qt * 128 + wm * 64 + mt * 16 + g + hr * 8;
                unsigned char* o = g_ctxp + (size_t)row * PROW_E + coff;
                *(uint32_t*)o = h2_of(acc[mt][nt][hr * 2 + 0], acc[mt][nt][hr * 2 + 1]);
            }
        }
    }
}

// ---------------- block means of post-RoPE q, k -----------------------------
__global__ void k_blockmean() {
    int idx = blockIdx.x * 256 + threadIdx.x;
    if (idx >= H_ * NB_ * D_) return;
    int d  = idx & 127;
    int nb = (idx >> 7) & 31;
    int h  = idx >> 12;
    float sq = 0.0f, sk = 0.0f;
    for (int r = 0; r < 64; r++) {
        size_t o = (size_t)(nb * 64 + r) * E_ + h * D_ + d;
        sq += g_q[o];
        sk += g_k[o];
    }
    g_qb[idx] = sq * (1.0f / 64.0f);
    g_kb[idx] = sk * (1.0f / 64.0f);
}

// ---------------- gate_pred --------------------------------------------------
__global__ __launch_bounds__(256) void k_gatepred(const float* __restrict__ Wgq,
                                                  const float* __restrict__ Wgk,
                                                  float* __restrict__ out) {
    const int h = blockIdx.x, tid = threadIdx.x;
    __shared__ float sgq[32 * 64];
    __shared__ float sgk[32 * 64];
    __shared__ float slog[1024];
    __shared__ float red[256];
    for (int t = tid; t < 2048; t += 256) {
        int nb = t >> 6, g = t & 63;
        float aq = 0.0f, ak = 0.0f;
        const float* qb = &g_qb[h * 4096 + nb * 128];
        const float* kb = &g_kb[h * 4096 + nb * 128];
        const float* w1 = &Wgq[g * 128];
        const float* w2 = &Wgk[g * 128];
#pragma unroll 4
        for (int d = 0; d < 128; d++) {
            aq = fmaf(qb[d], w1[d], aq);
            ak = fmaf(kb[d], w2[d], ak);
        }
        sgq[nb * 64 + g] = aq;
        sgk[nb * 64 + g] = ak;
    }
    __syncthreads();
    for (int t = tid; t < 1024; t += 256) {
        int nq = t >> 5, nk = t & 31;
        float v;
        if (nk <= nq) {
            v = 0.0f;
#pragma unroll 8
            for (int g = 0; g < 64; g++) v = fmaf(sgq[nq * 64 + g], sgk[nk * 64 + g], v);
            v *= 0.125f;
        } else {
            v = -INFINITY;
        }
        slog[t] = v;
    }
    __syncthreads();
    float m = -INFINITY;
    for (int t = tid; t < 1024; t += 256) m = fmaxf(m, slog[t]);
    float mx = blockReduceMax(m, red);
    float sum = 0.0f;
    for (int t = tid; t < 1024; t += 256) {
        float p = expf(slog[t] - mx);
        slog[t] = p;
        sum += p;
    }
    float s = blockReduceSum(sum, red);
    float inv = 1.0f / s;
    for (int t = tid; t < 1024; t += 256) out[h * 1024 + t] = slog[t] * inv;
}

// ---------------- gate_target ------------------------------------------------
__global__ __launch_bounds__(256) void k_gatetarget(float* __restrict__ out) {
    const int h = blockIdx.x, tid = threadIdx.x;
    __shared__ float sx[1024];
    __shared__ float red[256];
    for (int t = tid; t < 1024; t += 256) {
        int nq = t >> 5, nk = t & 31;
        float v;
        if (nk <= nq) {
            v = g_bmax[h * 1024 + t];
            v = fminf(fmaxf(v, -50.0f), 50.0f);
            v *= 0.5f;
        } else {
            v = -INFINITY;
        }
        sx[t] = v;
    }
    __syncthreads();
    float m = -INFINITY;
    for (int t = tid; t < 1024; t += 256) m = fmaxf(m, sx[t]);
    float mx = blockReduceMax(m, red);
    float sum = 0.0f;
    for (int t = tid; t < 1024; t += 256) {
        float p = expf(sx[t] - mx);
        sx[t] = p;
        sum += p;
    }
    float s = blockReduceSum(sum, red);
    float inv = 1.0f / s;
    for (int t = tid; t < 1024; t += 256) out[h * 1024 + t] = sx[t] * inv;
}

// ---------------- launch ------------------------------------------------------
extern "C" void kernel_launch(void* const* d_in, const int* in_sizes, int n_in,
                              void* d_out, int out_size) {
    const float* hs   = (const float*)d_in[0];
    const float* cosp = (const float*)d_in[1];
    const float* sinp = (const float*)d_in[2];
    const float* Wq   = (const float*)d_in[3];
    const float* Wk   = (const float*)d_in[4];
    const float* Wv   = (const float*)d_in[5];
    const float* Wo   = (const float*)d_in[6];
    const float* Wgq  = (const float*)d_in[7];
    const float* Wgk  = (const float*)d_in[8];
    float* out = (float*)d_out;

    const int GP_OFF = S_ * E_;
    const int GT_OFF = GP_OFF + H_ * NB_ * NB_;

    cudaFuncSetAttribute(k_gemm3,      cudaFuncAttributeMaxDynamicSharedMemorySize, GSMEM);
    cudaFuncSetAttribute(k_scores_mma, cudaFuncAttributeMaxDynamicSharedMemorySize, MMA_SMEM);
    cudaFuncSetAttribute(k_ctx_mma,    cudaFuncAttributeMaxDynamicSharedMemorySize, MMA_SMEM);

    unsigned char *hsp, *wqp, *wkp, *wvp, *wop, *ctxp;
    float *qf, *kf, *vf;
    cudaGetSymbolAddress((void**)&hsp,  g_hsp);
    cudaGetSymbolAddress((void**)&wqp,  g_wqp);
    cudaGetSymbolAddress((void**)&wkp,  g_wkp);
    cudaGetSymbolAddress((void**)&wvp,  g_wvp);
    cudaGetSymbolAddress((void**)&wop,  g_wop);
    cudaGetSymbolAddress((void**)&ctxp, g_ctxp);
    cudaGetSymbolAddress((void**)&qf,   g_q);
    cudaGetSymbolAddress((void**)&kf,   g_k);
    cudaGetSymbolAddress((void**)&vf,   g_v);

    const int n8_hs = S_ * E_ / 8;
    const int n8_w  = E_ * E_ / 8;
    k_pack<<<(n8_hs + 255) / 256, 256>>>(hs, hsp, n8_hs);
    k_packw<<<dim3((n8_w + 255) / 256, 4), 256>>>(Wq, Wk, Wv, Wo,
                                                  wqp, wkp, wvp, wop, n8_w);

    dim3 ggrid3(E_ / 128, S_ / 128, 3);
    k_gemm3<<<ggrid3, 256, GSMEM>>>(hsp, wqp, wkp, wvp, qf, kf, vf);

    k_rope<<<(S_ * H_ * 64 + 255) / 256, 256>>>(cosp, sinp);
    k_packT<<<dim3(S_ / 64, D_ / 32, H_), 256>>>();

    k_scores_mma<<<dim3(16, 16, H_), 256, MMA_SMEM>>>();
    k_softmax<<<dim3(S_, H_), 256>>>();
    k_ctx_mma<<<dim3(16, H_), 256, MMA_SMEM>>>();

    dim3 ggrid1(E_ / 128, S_ / 128, 1);
    k_gemm3<<<ggrid1, 256, GSMEM>>>(ctxp, wop, wop, wop, out, out, out);

    k_blockmean<<<(H_ * NB_ * D_ + 255) / 256, 256>>>();
    k_gatepred<<<H_, 256>>>(Wgq, Wgk, out + GP_OFF);
    k_gatetarget<<<H_, 256>>>(out + GT_OFF);
}